// round 7
// baseline (speedup 1.0000x reference)
#include <cuda_runtime.h>

#define BB 128
#define TT 2048
#define DD 64
#define HH 128
#define OO 32

typedef unsigned long long ull;

// Scratch (allocation-free rule: __device__ globals)
__device__ float g_xp0[(size_t)BB * TT * HH];  // layer0 input projection
__device__ float g_h1[(size_t)BB * TT * HH];   // layer1 hidden states

// ---------------------------------------------------------------------------
// short tanh: no clamp needed (ex2(+inf)=inf -> rcp=0 -> t=1). ~1e-6 rel err.
__device__ __forceinline__ float fast_tanh(float x) {
    float ax = fabsf(x);
    float y  = ax * 2.8853900817779268f;   // 2*log2(e)
    float e;  asm("ex2.approx.f32 %0, %1;" : "=f"(e) : "f"(y));
    float d  = e + 1.0f;
    float r;  asm("rcp.approx.f32 %0, %1;" : "=f"(r) : "f"(d));
    float t  = fmaf(-2.0f, r, 1.0f);
    return copysignf(t, x);
}

// Half-row dot (64 of 128 elements), INTERLEAVED in 32B blocks: thread-half h
// covers elements {8j+4h .. 8j+4h+3 : j=0..15}. v half-ptr = v + 4h floats ->
// even/odd lanes read 16B-adjacent addresses: conflict-free broadcast pair.
// c0 folded into accumulator init (caller guarantees c0 != 0 only on one half).
__device__ __forceinline__ float dot64i_c0(const ull* w, const float* vh, float c0) {
    ull a0, a1 = 0ull;
    asm("mov.b64 %0, {%1, %2};" : "=l"(a0) : "f"(c0), "f"(0.0f));
#pragma unroll
    for (int j = 0; j < 16; j++) {
        ulonglong2 p = *(const ulonglong2*)(vh + 8 * j);   // 16B at base+32j
        asm("fma.rn.f32x2 %0, %1, %2, %0;" : "+l"(a0) : "l"(w[2 * j]),     "l"(p.x));
        asm("fma.rn.f32x2 %0, %1, %2, %0;" : "+l"(a1) : "l"(w[2 * j + 1]), "l"(p.y));
    }
    asm("add.rn.f32x2 %0, %0, %1;" : "+l"(a0) : "l"(a1));
    float lo = __uint_as_float((unsigned)(a0 & 0xffffffffu));
    float hi = __uint_as_float((unsigned)(a0 >> 32));
    return lo + hi;
}

// ---------------------------------------------------------------------------
// Kernel 1: xp0 = x @ Wih0^T + biases. At scalar-FFMA roofline — do not touch.
#define XPAD 132
__global__ void __launch_bounds__(256)
xproj_kernel(const float* __restrict__ x, const float* __restrict__ Wih0,
             const float* __restrict__ bih0, const float* __restrict__ bhh0) {
    extern __shared__ float sm[];
    float* xsT = sm;                 // [64][XPAD]
    float* wsT = sm + 64 * XPAD;     // [64][XPAD]
    int tid  = threadIdx.x;
    int row0 = blockIdx.x * 128;

    const float4* xg = (const float4*)(x + (size_t)row0 * DD);
#pragma unroll
    for (int j = 0; j < 8; j++) {
        int idx = tid + 256 * j;
        float4 v = xg[idx];
        int r = idx >> 4, d4 = (idx & 15) << 2;
        xsT[(d4 + 0) * XPAD + r] = v.x;
        xsT[(d4 + 1) * XPAD + r] = v.y;
        xsT[(d4 + 2) * XPAD + r] = v.z;
        xsT[(d4 + 3) * XPAD + r] = v.w;
    }
    const float4* wg = (const float4*)Wih0;
#pragma unroll
    for (int j = 0; j < 8; j++) {
        int idx = tid + 256 * j;
        float4 v = wg[idx];
        int h = idx >> 4, d4 = (idx & 15) << 2;
        wsT[(d4 + 0) * XPAD + h] = v.x;
        wsT[(d4 + 1) * XPAD + h] = v.y;
        wsT[(d4 + 2) * XPAD + h] = v.z;
        wsT[(d4 + 3) * XPAD + h] = v.w;
    }

    int tx = tid & 15, ty = tid >> 4;
    int c0 = tx * 8, r0 = ty * 8;
    float acc[8][8];
#pragma unroll
    for (int j = 0; j < 8; j++) {
        float bb = bih0[c0 + j] + bhh0[c0 + j];
#pragma unroll
        for (int i = 0; i < 8; i++) acc[i][j] = bb;
    }
    __syncthreads();

#pragma unroll 8
    for (int k = 0; k < 64; k++) {
        float4 a0 = *(const float4*)&xsT[k * XPAD + r0];
        float4 a1 = *(const float4*)&xsT[k * XPAD + r0 + 4];
        float4 b0 = *(const float4*)&wsT[k * XPAD + c0];
        float4 b1 = *(const float4*)&wsT[k * XPAD + c0 + 4];
        float av[8] = {a0.x, a0.y, a0.z, a0.w, a1.x, a1.y, a1.z, a1.w};
        float bv[8] = {b0.x, b0.y, b0.z, b0.w, b1.x, b1.y, b1.z, b1.w};
#pragma unroll
        for (int i = 0; i < 8; i++)
#pragma unroll
            for (int j = 0; j < 8; j++)
                acc[i][j] = fmaf(av[i], bv[j], acc[i][j]);
    }

    float* og = g_xp0 + (size_t)row0 * HH;
#pragma unroll
    for (int i = 0; i < 8; i++) {
        *(float4*)&og[(size_t)(r0 + i) * HH + c0] =
            make_float4(acc[i][0], acc[i][1], acc[i][2], acc[i][3]);
        *(float4*)&og[(size_t)(r0 + i) * HH + c0 + 4] =
            make_float4(acc[i][4], acc[i][5], acc[i][6], acc[i][7]);
    }
}

// ---------------------------------------------------------------------------
// Kernel 2: sequential scan, SPLIT-ROW layout: 768 threads, 2 threads per row
// (halves on adjacent lanes, shfl_xor(1) reduce). 3 groups x 256 threads,
// R3 dataflow (1-step skew, one __syncthreads per step, branch-free body).
// Per-thread: 32 ull weights (64 regs) -> fits the 65536/768=85 reg budget.
__global__ void __launch_bounds__(768, 1)
scan_kernel(const float* __restrict__ Whh0, const float* __restrict__ Wih1,
            const float* __restrict__ Whh1, const float* __restrict__ bih1,
            const float* __restrict__ bhh1, const int* __restrict__ lengths) {
    __shared__ __align__(16) float sbuf[6 * HH];
    float* h0buf = sbuf;            // [2][HH]
    float* h1buf = sbuf + 2 * HH;   // [2][HH]
    float* p1buf = sbuf + 4 * HH;   // [2][HH]

    int b   = blockIdx.x;
    int L   = lengths[b];
    int tid = threadIdx.x;
    int grp = tid >> 8;        // 0,1,2
    int rh  = tid & 255;
    int row = rh >> 1;
    int h   = rh & 1;          // row half; halves on adjacent lanes
    bool isg0 = (grp == 0), isg1 = (grp == 1), isg2 = (grp == 2);

    // Interleaved weight load: w[2j],w[2j+1] = row elements [8j+4h .. 8j+4h+3]
    const ull* W64 = (const ull*)((isg0 ? Whh0 : (isg1 ? Wih1 : Whh1))
                                  + (size_t)row * HH) + 2 * h;
    ull w[32];
#pragma unroll
    for (int j = 0; j < 16; j++) { w[2 * j] = W64[4 * j]; w[2 * j + 1] = W64[4 * j + 1]; }

    // c0 ring (2-deep): g0/h0 = streamed xp; g1/h0 = bias; all others = 0,
    // so c0 enters exactly one half-partial per row.
    const float* xp_base = g_xp0 + (size_t)b * TT * HH + row;
    float xp[2];
    if (isg0 && h == 0) { xp[0] = xp_base[0]; xp[1] = xp_base[HH]; }
    else {
        float cinit = (isg1 && h == 0) ? (bih1[row] + bhh1[row]) : 0.f;
        xp[0] = cinit; xp[1] = cinit;
    }

    if (isg0 && h == 0) h0buf[HH + row] = 0.f;   // value -1 in buffer 1
    if (isg2 && h == 0) h1buf[HH + row] = 0.f;

    // parity-indexed half-vector read ptrs + store ptrs (pa = s&1):
    //   g0: read h0buf[pb], write h0buf[pa]
    //   g1: read h0buf[pb], write p1buf[pb]
    //   g2: read h1buf[pb], write h1buf[pa], extra-read p1buf[pa]
    const float* vrd[2];
    float*       st[2];
    const float* prd[2];
#pragma unroll
    for (int pa = 0; pa < 2; pa++) {
        int pb = pa ^ 1;
        vrd[pa] = (isg2 ? h1buf : h0buf) + pb * HH + 4 * h;  // interleave offset
        st[pa]  = (isg0 ? h0buf + pa * HH : (isg1 ? p1buf + pb * HH
                                                  : h1buf + pa * HH)) + row;
        prd[pa] = p1buf + pa * HH + row;
    }
    float* h1out = g_h1 + (size_t)b * TT * HH + row;

    __syncthreads();   // initial state visible to everyone

    int spad = ((L + 2) + 3) & ~3;
    for (int s0 = 0; s0 < spad; s0 += 4) {
#pragma unroll
        for (int u = 0; u < 4; u++) {
            int s  = s0 + u;
            int pa = u & 1;                       // static after unroll
            float extra = *prd[pa];               // p1 value s-2 (g2 use)
            float part  = dot64i_c0(w, vrd[pa], xp[pa]);
            part += __shfl_xor_sync(0xffffffffu, part, 1);   // cross-half sum
            float pre = part + (isg2 ? extra : 0.f);
            float th  = fast_tanh(pre);
            float y   = isg1 ? pre : th;
            if (h == 0 && (!isg2 || s >= 2)) *st[pa] = y;    // predicated STS
            if (isg2 && h == 0 && (unsigned)(s - 2) < (unsigned)TT)
                h1out[(size_t)(s - 2) * HH] = y;             // predicated STG
            if (isg0 && h == 0) {                            // prefetch dist 2
                int nidx = s + 2; if (nidx > TT - 1) nidx = TT - 1;
                xp[pa] = __ldg(&xp_base[(size_t)nidx * HH]);
            }
            __syncthreads();
        }
    }
}

// ---------------------------------------------------------------------------
// Kernel 3: out[b,t,:] = (t < L) ? h1[b,t,:] @ W_fc^T + b_fc : b_fc
__global__ void __launch_bounds__(256)
fc_kernel(const float* __restrict__ Wfc, const float* __restrict__ bfc,
          const int* __restrict__ lengths, float* __restrict__ out) {
    __shared__ __align__(16) float wfcT[HH * 33];
    __shared__ __align__(16) float h1s[32 * HH];
    __shared__ float bfcs[OO];

    int tid  = threadIdx.x;
    int row0 = blockIdx.x * 32;      // 32 | TT -> whole block is one batch b
    int b = row0 / TT;
    int L = lengths[b];

    for (int idx = tid; idx < OO * HH; idx += 256) {
        int o = idx >> 7, k = idx & 127;
        wfcT[k * 33 + o] = Wfc[idx];
    }
    if (tid < OO) bfcs[tid] = bfc[tid];
    const float4* hg = (const float4*)(g_h1 + (size_t)row0 * HH);
#pragma unroll
    for (int j = 0; j < 4; j++)
        ((float4*)h1s)[tid + 256 * j] = hg[tid + 256 * j];
    __syncthreads();

    int o  = tid & 31;
    int rg = tid >> 5;               // 8 groups x 4 rows
    int tb = row0 % TT;
#pragma unroll
    for (int i = 0; i < 4; i++) {
        int r = rg * 4 + i;
        int t = tb + r;
        float res;
        if (t < L) {
            float acc = 0.f;
#pragma unroll
            for (int k = 0; k < HH; k++)
                acc = fmaf(wfcT[k * 33 + o], h1s[r * HH + k], acc);
            res = acc + bfcs[o];
        } else {
            res = bfcs[o];
        }
        out[(size_t)(row0 + r) * OO + o] = res;
    }
}

// ---------------------------------------------------------------------------
extern "C" void kernel_launch(void* const* d_in, const int* in_sizes, int n_in,
                              void* d_out, int out_size) {
    const float* x     = (const float*)d_in[0];
    const int*   len   = (const int*)  d_in[1];
    const float* Wih0  = (const float*)d_in[2];
    const float* Whh0  = (const float*)d_in[3];
    const float* bih0  = (const float*)d_in[4];
    const float* bhh0  = (const float*)d_in[5];
    const float* Wih1  = (const float*)d_in[6];
    const float* Whh1  = (const float*)d_in[7];
    const float* bih1  = (const float*)d_in[8];
    const float* bhh1  = (const float*)d_in[9];
    const float* Wfc   = (const float*)d_in[10];
    const float* bfc   = (const float*)d_in[11];
    float* out = (float*)d_out;

    static_assert(2 * 64 * XPAD * 4 == 67584, "smem size");
    cudaFuncSetAttribute(xproj_kernel, cudaFuncAttributeMaxDynamicSharedMemorySize, 67584);
    xproj_kernel<<<(BB * TT) / 128, 256, 67584>>>(x, Wih0, bih0, bhh0);
    scan_kernel<<<BB, 768>>>(Whh0, Wih1, Whh1, bih1, bhh1, len);
    fc_kernel<<<(BB * TT) / 32, 256>>>(Wfc, bfc, len, out);
}

// round 9
// speedup vs baseline: 1.2618x; 1.2618x over previous
#include <cuda_runtime.h>
#include <cstdint>

#define BB 128
#define TT 2048
#define DD 64
#define HH 128
#define OO 32

typedef unsigned long long ull;

// Scratch (allocation-free rule: __device__ globals)
__device__ float g_xp0[(size_t)BB * TT * HH];  // layer0 input projection
__device__ float g_h1[(size_t)BB * TT * HH];   // layer1 hidden states

// ---------------------------------------------------------------------------
// short tanh: no clamp needed (ex2(+inf)=inf -> rcp=0 -> t=1). ~1e-6 rel err.
__device__ __forceinline__ float fast_tanh(float x) {
    float ax = fabsf(x);
    float y  = ax * 2.8853900817779268f;   // 2*log2(e)
    float e;  asm("ex2.approx.f32 %0, %1;" : "=f"(e) : "f"(y));
    float d  = e + 1.0f;
    float r;  asm("rcp.approx.f32 %0, %1;" : "=f"(r) : "f"(d));
    float t  = fmaf(-2.0f, r, 1.0f);
    return copysignf(t, x);
}

// 128-long dot, c0 folded into accumulator init. Weights in regs as 64 packed
// f32x2; vector from smem via LDS.128 broadcast. 2 accumulator chains.
__device__ __forceinline__ float dot128_c0(const ull* w, const float* v, float c0) {
    ull a0, a1 = 0ull;
    asm("mov.b64 %0, {%1, %2};" : "=l"(a0) : "f"(c0), "f"(0.0f));
    const ulonglong2* v2 = (const ulonglong2*)v;
#pragma unroll
    for (int j = 0; j < 32; j++) {
        ulonglong2 p = v2[j];
        asm("fma.rn.f32x2 %0, %1, %2, %0;" : "+l"(a0) : "l"(w[2 * j]),     "l"(p.x));
        asm("fma.rn.f32x2 %0, %1, %2, %0;" : "+l"(a1) : "l"(w[2 * j + 1]), "l"(p.y));
    }
    asm("add.rn.f32x2 %0, %0, %1;" : "+l"(a0) : "l"(a1));
    float lo = __uint_as_float((unsigned)(a0 & 0xffffffffu));
    float hi = __uint_as_float((unsigned)(a0 >> 32));
    return lo + hi;
}

__device__ __forceinline__ uint32_t smem_u32(const void* p) {
    uint32_t a;
    asm("{ .reg .u64 t; cvta.to.shared.u64 t, %1; cvt.u32.u64 %0, t; }"
        : "=r"(a) : "l"(p));
    return a;
}

__device__ __forceinline__ void spin_ge(uint32_t addr, int target) {
    int v;
    asm volatile("ld.acquire.cta.shared.b32 %0, [%1];" : "=r"(v) : "r"(addr) : "memory");
    while (v < target) {
        __nanosleep(20);
        asm volatile("ld.acquire.cta.shared.b32 %0, [%1];" : "=r"(v) : "r"(addr) : "memory");
    }
}

__device__ __forceinline__ void rel_store(uint32_t addr, int val) {
    asm volatile("st.release.cta.shared.b32 [%0], %1;" :: "r"(addr), "r"(val) : "memory");
}

// ---------------------------------------------------------------------------
// Kernel 1: xp0 = x @ Wih0^T + biases. At scalar-FFMA roofline — unchanged.
#define XPAD 132
__global__ void __launch_bounds__(256)
xproj_kernel(const float* __restrict__ x, const float* __restrict__ Wih0,
             const float* __restrict__ bih0, const float* __restrict__ bhh0) {
    extern __shared__ float sm[];
    float* xsT = sm;
    float* wsT = sm + 64 * XPAD;
    int tid  = threadIdx.x;
    int row0 = blockIdx.x * 128;

    const float4* xg = (const float4*)(x + (size_t)row0 * DD);
#pragma unroll
    for (int j = 0; j < 8; j++) {
        int idx = tid + 256 * j;
        float4 v = xg[idx];
        int r = idx >> 4, d4 = (idx & 15) << 2;
        xsT[(d4 + 0) * XPAD + r] = v.x;
        xsT[(d4 + 1) * XPAD + r] = v.y;
        xsT[(d4 + 2) * XPAD + r] = v.z;
        xsT[(d4 + 3) * XPAD + r] = v.w;
    }
    const float4* wg = (const float4*)Wih0;
#pragma unroll
    for (int j = 0; j < 8; j++) {
        int idx = tid + 256 * j;
        float4 v = wg[idx];
        int h = idx >> 4, d4 = (idx & 15) << 2;
        wsT[(d4 + 0) * XPAD + h] = v.x;
        wsT[(d4 + 1) * XPAD + h] = v.y;
        wsT[(d4 + 2) * XPAD + h] = v.z;
        wsT[(d4 + 3) * XPAD + h] = v.w;
    }

    int tx = tid & 15, ty = tid >> 4;
    int c0 = tx * 8, r0 = ty * 8;
    float acc[8][8];
#pragma unroll
    for (int j = 0; j < 8; j++) {
        float bb = bih0[c0 + j] + bhh0[c0 + j];
#pragma unroll
        for (int i = 0; i < 8; i++) acc[i][j] = bb;
    }
    __syncthreads();

#pragma unroll 8
    for (int k = 0; k < 64; k++) {
        float4 a0 = *(const float4*)&xsT[k * XPAD + r0];
        float4 a1 = *(const float4*)&xsT[k * XPAD + r0 + 4];
        float4 b0 = *(const float4*)&wsT[k * XPAD + c0];
        float4 b1 = *(const float4*)&wsT[k * XPAD + c0 + 4];
        float av[8] = {a0.x, a0.y, a0.z, a0.w, a1.x, a1.y, a1.z, a1.w};
        float bv[8] = {b0.x, b0.y, b0.z, b0.w, b1.x, b1.y, b1.z, b1.w};
#pragma unroll
        for (int i = 0; i < 8; i++)
#pragma unroll
            for (int j = 0; j < 8; j++)
                acc[i][j] = fmaf(av[i], bv[j], acc[i][j]);
    }

    float* og = g_xp0 + (size_t)row0 * HH;
#pragma unroll
    for (int i = 0; i < 8; i++) {
        *(float4*)&og[(size_t)(r0 + i) * HH + c0] =
            make_float4(acc[i][0], acc[i][1], acc[i][2], acc[i][3]);
        *(float4*)&og[(size_t)(r0 + i) * HH + c0 + 4] =
            make_float4(acc[i][4], acc[i][5], acc[i][6], acc[i][7]);
    }
}

// ---------------------------------------------------------------------------
// Kernel 2: sequential scan, ASYNC producer/consumer groups.
//   Group A (tid 0..127): layer0 recurrence; 4-deep h0 ring; bar.sync 1,128;
//       publishes counter c0 = steps completed (h0 value s published => c0>=s+1).
//   Group B (tid 128..383): layer1; lane pairs (even=Wih1 row, odd=Whh1 row),
//       shfl_xor(1) combine; 2-deep h1 ring (+16B bank offset); bar.sync 2,256;
//       publishes cB. B step k computes h1[k] from h0[k], h1[k-1].
// Waits: B: c0 >= k+1.  A (s>=4): cB >= s-3 (WAR on 4-deep h0 ring).
// Smem byte layout: h0 ring 4x512 @0; h1 ring 2x512 @2064,2576; c0@3088 cB@3092.
__global__ void __launch_bounds__(384, 1)
scan_kernel(const float* __restrict__ Whh0, const float* __restrict__ Wih1,
            const float* __restrict__ Whh1, const float* __restrict__ bih1,
            const float* __restrict__ bhh1, const int* __restrict__ lengths) {
    __shared__ __align__(1024) unsigned char sb[3104];
    float* h0r[4];
    float* h1r[2];
#pragma unroll
    for (int i = 0; i < 4; i++) h0r[i] = (float*)(sb + 512 * i);
#pragma unroll
    for (int i = 0; i < 2; i++) h1r[i] = (float*)(sb + 2064 + 512 * i);
    uint32_t c0a = smem_u32(sb + 3088);
    uint32_t cba = smem_u32(sb + 3092);

    int b   = blockIdx.x;
    int L   = lengths[b];
    int tid = threadIdx.x;
    bool isA = (tid < 128);

    // zero init: h0 value -1 -> slot 3; h1 value -1 -> slot 1; counters
    if (tid < 128) h0r[3][tid] = 0.f;
    else if (tid < 256) h1r[1][tid - 128] = 0.f;
    if (tid == 0) { *(int*)(sb + 3088) = 0; *(int*)(sb + 3092) = 0; }
    __syncthreads();

    int spad = ((L + 3) & ~3);
    if (spad < 4) spad = 4;

    if (isA) {
        // ---------------- Group A: layer0 ----------------
        int row = tid;
        const ull* W64 = (const ull*)(Whh0 + (size_t)row * HH);
        ull w[64];
#pragma unroll
        for (int j = 0; j < 64; j++) w[j] = W64[j];

        const float* xp_base = g_xp0 + (size_t)b * TT * HH + row;
        float xp[4];
#pragma unroll
        for (int i = 0; i < 4; i++) xp[i] = xp_base[(size_t)i * HH];

        for (int s0 = 0; s0 < spad; s0 += 4) {
#pragma unroll
            for (int u = 0; u < 4; u++) {
                int s = s0 + u;
                if (s >= 4) spin_ge(cba, s - 3);      // WAR vs B on ring slot
                float d = dot128_c0(w, h0r[(u + 3) & 3], xp[u]);
                float h = fast_tanh(d);
                h0r[u][row] = h;                      // h0 value s -> slot s&3
                int nidx = s + 4; if (nidx > TT - 1) nidx = TT - 1;
                xp[u] = __ldg(&xp_base[(size_t)nidx * HH]);
                asm volatile("bar.sync 1, 128;" ::: "memory");
                if (row == 0) rel_store(c0a, s + 1);
            }
        }
    } else {
        // ---------------- Group B: layer1 ----------------
        int j   = tid - 128;
        int row = j >> 1;
        int par = j & 1;            // 0: Wih1 (c0=bias), 1: Whh1 (c0=0)
        const ull* W64 = (const ull*)((par ? Whh1 : Wih1) + (size_t)row * HH);
        ull w[64];
#pragma unroll
        for (int jj = 0; jj < 64; jj++) w[jj] = W64[jj];

        float cini = par ? 0.f : (bih1[row] + bhh1[row]);
        float* h1out = g_h1 + (size_t)b * TT * HH + row;

        // per-u vector pointers: even reads h0 slot k&3 = u; odd reads h1
        // slot (k-1)&1 = (u+1)&1
        const float* vrd[4];
#pragma unroll
        for (int u = 0; u < 4; u++)
            vrd[u] = par ? h1r[(u + 1) & 1] : h0r[u];

        for (int k0 = 0; k0 < spad; k0 += 4) {
#pragma unroll
            for (int u = 0; u < 4; u++) {
                int k = k0 + u;
                spin_ge(c0a, k + 1);                  // h0 value k available
                float part = dot128_c0(w, vrd[u], cini);
                float pre  = part + __shfl_xor_sync(0xffffffffu, part, 1);
                float h    = fast_tanh(pre);
                if (par == 0) h1r[u & 1][row] = h;    // h1 value k -> slot k&1
                else if (k < L) h1out[(size_t)k * HH] = h;
                asm volatile("bar.sync 2, 256;" ::: "memory");
                if (j == 0) rel_store(cba, k + 1);
            }
        }
    }
}

// ---------------------------------------------------------------------------
// Kernel 3: out[b,t,:] = (t < L) ? h1[b,t,:] @ W_fc^T + b_fc : b_fc
__global__ void __launch_bounds__(256)
fc_kernel(const float* __restrict__ Wfc, const float* __restrict__ bfc,
          const int* __restrict__ lengths, float* __restrict__ out) {
    __shared__ __align__(16) float wfcT[HH * 33];
    __shared__ __align__(16) float h1s[32 * HH];
    __shared__ float bfcs[OO];

    int tid  = threadIdx.x;
    int row0 = blockIdx.x * 32;      // 32 | TT -> whole block is one batch b
    int b = row0 / TT;
    int L = lengths[b];

    for (int idx = tid; idx < OO * HH; idx += 256) {
        int o = idx >> 7, k = idx & 127;
        wfcT[k * 33 + o] = Wfc[idx];
    }
    if (tid < OO) bfcs[tid] = bfc[tid];
    const float4* hg = (const float4*)(g_h1 + (size_t)row0 * HH);
#pragma unroll
    for (int j = 0; j < 4; j++)
        ((float4*)h1s)[tid + 256 * j] = hg[tid + 256 * j];
    __syncthreads();

    int o  = tid & 31;
    int rg = tid >> 5;
    int tb = row0 % TT;
#pragma unroll
    for (int i = 0; i < 4; i++) {
        int r = rg * 4 + i;
        int t = tb + r;
        float res;
        if (t < L) {
            float acc = 0.f;
#pragma unroll
            for (int k = 0; k < HH; k++)
                acc = fmaf(wfcT[k * 33 + o], h1s[r * HH + k], acc);
            res = acc + bfcs[o];
        } else {
            res = bfcs[o];
        }
        out[(size_t)(row0 + r) * OO + o] = res;
    }
}

// ---------------------------------------------------------------------------
extern "C" void kernel_launch(void* const* d_in, const int* in_sizes, int n_in,
                              void* d_out, int out_size) {
    const float* x     = (const float*)d_in[0];
    const int*   len   = (const int*)  d_in[1];
    const float* Wih0  = (const float*)d_in[2];
    const float* Whh0  = (const float*)d_in[3];
    const float* bih0  = (const float*)d_in[4];
    const float* bhh0  = (const float*)d_in[5];
    const float* Wih1  = (const float*)d_in[6];
    const float* Whh1  = (const float*)d_in[7];
    const float* bih1  = (const float*)d_in[8];
    const float* bhh1  = (const float*)d_in[9];
    const float* Wfc   = (const float*)d_in[10];
    const float* bfc   = (const float*)d_in[11];
    float* out = (float*)d_out;

    cudaFuncSetAttribute(xproj_kernel, cudaFuncAttributeMaxDynamicSharedMemorySize, 67584);
    xproj_kernel<<<(BB * TT) / 128, 256, 67584>>>(x, Wih0, bih0, bhh0);
    scan_kernel<<<BB, 384>>>(Whh0, Wih1, Whh1, bih1, bhh1, len);
    fc_kernel<<<(BB * TT) / 32, 256>>>(Wfc, bfc, len, out);
}